// round 9
// baseline (speedup 1.0000x reference)
#include <cuda_runtime.h>
#include <cstdint>
#include <cstddef>

// Problem constants
#define NN 10000
#define KK 16
#define MEAN_NODES 625.0f

// Main kernel geometry
#define THREADS 768
#define CPT 2
#define COLS 1536                     // cols per j-slice (= THREADS*CPT)
#define NBLK_J 7                      // slices at j0 = b*1536, last at 8464 (ends 10000)
#define NBLK_I 21
#define IT 480                        // rows per i-tile (21*480 = 10080, clamp+zero tail)
#define RPS 4                         // rows per stage
#define NCH (IT / RPS)                // 120 chunks
#define NS 6                          // pipeline stages
#define ROWB (COLS * 4)               // 6144 bytes per row slice
#define STAGEB (RPS * ROWB)           // 24576 bytes per stage
#define PBLOCKS 40
#define GRID_MAIN (NBLK_J * NBLK_I)   // 147

// dynamic smem layout
#define SM_MBAR 0                     // 6 mbarriers (8B each)
#define SM_STG  1024                  // 6 stages x 24576 = 147456
#define SM_YN   (SM_STG + NS * STAGEB)            // 148480
#define SMEM_TOTAL (SM_YN + IT * KK * 4)          // 179200 B

// Device-global scratch
__device__ double g_cut;
__device__ float  g_invg[KK];
__device__ float  g_ep;
__device__ float  g_part[PBLOCKS * 32];
__device__ unsigned int g_ctr_p;
__device__ unsigned int g_ctr_m;

// ---- packed f32x2 helpers (Blackwell FFMA2) ----
__device__ __forceinline__ unsigned long long ffma2(unsigned long long a,
                                                    unsigned long long b,
                                                    unsigned long long c) {
    unsigned long long d;
    asm("fma.rn.f32x2 %0, %1, %2, %3;" : "=l"(d) : "l"(a), "l"(b), "l"(c));
    return d;
}
__device__ __forceinline__ unsigned long long pack2(float x, float y) {
    unsigned long long d;
    asm("mov.b64 %0, {%1, %2};" : "=l"(d) : "f"(x), "f"(y));
    return d;
}
__device__ __forceinline__ float2 unpack2(unsigned long long v) {
    float2 r;
    asm("mov.b64 {%0, %1}, %2;" : "=f"(r.x), "=f"(r.y) : "l"(v));
    return r;
}

// ---- smem / mbarrier / bulk-copy helpers ----
__device__ __forceinline__ uint32_t smem_u32(const void* p) {
    uint32_t a;
    asm("{ .reg .u64 t; cvta.to.shared.u64 t, %1; cvt.u32.u64 %0, t; }"
        : "=r"(a) : "l"(p));
    return a;
}
__device__ __forceinline__ void mbar_init(uint32_t a, uint32_t cnt) {
    asm volatile("mbarrier.init.shared.b64 [%0], %1;" :: "r"(a), "r"(cnt) : "memory");
}
__device__ __forceinline__ void mbar_expect_tx(uint32_t a, uint32_t bytes) {
    asm volatile("mbarrier.arrive.expect_tx.shared.b64 _, [%0], %1;"
                 :: "r"(a), "r"(bytes) : "memory");
}
__device__ __forceinline__ void mbar_wait(uint32_t a, uint32_t parity) {
    asm volatile(
        "{\n\t.reg .pred P;\n\tLW_%=:\n\t"
        "mbarrier.try_wait.parity.acquire.cta.shared::cta.b64 P, [%0], %1, 0x989680;\n\t"
        "@!P bra LW_%=;\n\t}"
        :: "r"(a), "r"(parity) : "memory");
}
__device__ __forceinline__ void bulk_cp(uint32_t dst, const void* src,
                                        uint32_t bytes, uint32_t mbar) {
    asm volatile(
        "cp.async.bulk.shared::cluster.global.mbarrier::complete_tx::bytes "
        "[%0], [%1], %2, [%3];"
        :: "r"(dst), "l"(src), "r"(bytes), "r"(mbar) : "memory");
}

// ============================================================
// Kernel 1: partials of gamma[k] and colsum[k]; last block finalizes.
// ============================================================
__global__ void k_partial(const float* __restrict__ Y,
                          const float* __restrict__ deg) {
    int i = blockIdx.x * 256 + threadIdx.x;
    float g[KK], c[KK];
#pragma unroll
    for (int k = 0; k < KK; k++) { g[k] = 0.f; c[k] = 0.f; }

    if (i < NN) {
        float d = deg[i];
        const float4* yr = (const float4*)(Y + (size_t)i * KK);
#pragma unroll
        for (int q = 0; q < 4; q++) {
            float4 v = yr[q];
            c[q * 4 + 0] = v.x; c[q * 4 + 1] = v.y;
            c[q * 4 + 2] = v.z; c[q * 4 + 3] = v.w;
            g[q * 4 + 0] = v.x * d; g[q * 4 + 1] = v.y * d;
            g[q * 4 + 2] = v.z * d; g[q * 4 + 3] = v.w * d;
        }
    }
#pragma unroll
    for (int k = 0; k < KK; k++) {
#pragma unroll
        for (int o = 16; o; o >>= 1) {
            g[k] += __shfl_xor_sync(0xffffffffu, g[k], o);
            c[k] += __shfl_xor_sync(0xffffffffu, c[k], o);
        }
    }
    __shared__ float red[8][32];
    __shared__ bool  is_last;
    int warp = threadIdx.x >> 5, lane = threadIdx.x & 31;
    if (lane == 0) {
#pragma unroll
        for (int k = 0; k < KK; k++) {
            red[warp][k]      = g[k];
            red[warp][16 + k] = c[k];
        }
    }
    __syncthreads();
    if (threadIdx.x < 32) {
        float s = 0.f;
#pragma unroll
        for (int w = 0; w < 8; w++) s += red[w][threadIdx.x];
        g_part[blockIdx.x * 32 + threadIdx.x] = s;
    }
    __threadfence();
    if (threadIdx.x == 0) {
        unsigned int old = atomicAdd(&g_ctr_p, 1u);
        is_last = (old == PBLOCKS - 1);
    }
    __syncthreads();
    if (is_last && threadIdx.x < 32) {
        __threadfence();
        int t = threadIdx.x;
        const volatile float* gp = g_part;
        float s = 0.f;
        for (int b = 0; b < PBLOCKS; b++) s += gp[b * 32 + t];
        red[0][t] = s;
        __syncwarp();
        if (t < KK) g_invg[t] = 1.0f / s;
        if (t == 0) {
            float e = 0.f;
#pragma unroll
            for (int k = 0; k < KK; k++) {
                float d2 = red[0][16 + k] - MEAN_NODES;
                e += d2 * d2;
            }
            g_ep   = e;
            g_cut  = 0.0;
            g_ctr_p = 0u;
        }
    }
}

// ============================================================
// Kernel 2: main pass. cp.async.bulk pipeline stages A row-slices
// into smem; thread owns column pair; yn row broadcast from smem.
// ============================================================
__global__ void __launch_bounds__(THREADS, 1)
k_main(const float* __restrict__ A, const float* __restrict__ Y,
       float* __restrict__ out) {
    extern __shared__ char smem[];
    const uint32_t sb  = smem_u32(smem);
    const int tid  = threadIdx.x;
    const int jb   = blockIdx.x;
    const int j0   = (jb < NBLK_J - 1) ? jb * COLS : (NN - COLS);  // 8464 last
    const int i0   = blockIdx.y * IT;
    const int iend = (NN - i0 < IT) ? (NN - i0) : IT;   // rows with real yn
    const int col0 = j0 + 2 * tid;

    // ---- mbarrier init ----
    if (tid == 0) {
#pragma unroll
        for (int s = 0; s < NS; s++) mbar_init(sb + SM_MBAR + 8 * s, 1);
    }

    // ---- cooperative yn tile: yn[i,k] = Y[i,k]*invg[k], zero beyond iend ----
    float* sYn = (float*)(smem + SM_YN);
    float4 iv[4];
#pragma unroll
    for (int q = 0; q < 4; q++) iv[q] = *(const float4*)(g_invg + q * 4);
    for (int idx = tid; idx < IT * 4; idx += THREADS) {
        int r = idx >> 2, c = idx & 3;
        int i = i0 + r;
        float4 v = make_float4(0.f, 0.f, 0.f, 0.f);
        if (i < NN) {
            float4 y = *(const float4*)(Y + (size_t)i * KK + c * 4);
            v = make_float4(y.x * iv[c].x, y.y * iv[c].y,
                            y.z * iv[c].z, y.w * iv[c].w);
        }
        *(float4*)(sYn + r * KK + c * 4) = v;
    }
    __syncthreads();   // mbars + yn visible

    // ---- producer: issue first NS chunks ----
    if (tid == 0) {
#pragma unroll
        for (int c = 0; c < NS; c++) {
            uint32_t mb = sb + SM_MBAR + 8 * c;
            mbar_expect_tx(mb, STAGEB);
#pragma unroll
            for (int r = 0; r < RPS; r++) {
                int row = i0 + c * RPS + r;
                if (row > NN - 1) row = NN - 1;   // clamp (dead data x zero yn)
                bulk_cp(sb + SM_STG + c * STAGEB + r * ROWB,
                        A + (size_t)row * NN + j0, ROWB, mb);
            }
        }
    }

    // ---- main pipeline loop ----
    unsigned long long acc0[8], acc1[8];
#pragma unroll
    for (int p = 0; p < 8; p++) { acc0[p] = 0ULL; acc1[p] = 0ULL; }

    uint32_t ph = 0;   // per-stage parity bits
    int s = 0;
#pragma unroll 1
    for (int c = 0; c < NCH; c++) {
        const uint32_t mb = sb + SM_MBAR + 8 * s;
        mbar_wait(mb, (ph >> s) & 1u);
        ph ^= (1u << s);

        const char*  stg = smem + SM_STG + s * STAGEB;
        const float* syn = sYn + c * RPS * KK;
#pragma unroll
        for (int r = 0; r < RPS; r++) {
            float2 a = *(const float2*)(stg + r * ROWB + tid * 8);
            const ulonglong2* yp = (const ulonglong2*)(syn + r * KK);
            ulonglong2 y0 = yp[0], y1 = yp[1], y2 = yp[2], y3 = yp[3];
            unsigned long long a0 = pack2(a.x, a.x);
            unsigned long long a1 = pack2(a.y, a.y);
            acc0[0] = ffma2(a0, y0.x, acc0[0]);
            acc0[1] = ffma2(a0, y0.y, acc0[1]);
            acc0[2] = ffma2(a0, y1.x, acc0[2]);
            acc0[3] = ffma2(a0, y1.y, acc0[3]);
            acc0[4] = ffma2(a0, y2.x, acc0[4]);
            acc0[5] = ffma2(a0, y2.y, acc0[5]);
            acc0[6] = ffma2(a0, y3.x, acc0[6]);
            acc0[7] = ffma2(a0, y3.y, acc0[7]);
            acc1[0] = ffma2(a1, y0.x, acc1[0]);
            acc1[1] = ffma2(a1, y0.y, acc1[1]);
            acc1[2] = ffma2(a1, y1.x, acc1[2]);
            acc1[3] = ffma2(a1, y1.y, acc1[3]);
            acc1[4] = ffma2(a1, y2.x, acc1[4]);
            acc1[5] = ffma2(a1, y2.y, acc1[5]);
            acc1[6] = ffma2(a1, y3.x, acc1[6]);
            acc1[7] = ffma2(a1, y3.y, acc1[7]);
        }
        __syncthreads();   // all threads done reading stage s

        if (tid == 0 && c + NS < NCH) {
            mbar_expect_tx(mb, STAGEB);
#pragma unroll
            for (int r = 0; r < RPS; r++) {
                int row = i0 + (c + NS) * RPS + r;
                if (row > NN - 1) row = NN - 1;
                bulk_cp(sb + SM_STG + s * STAGEB + r * ROWB,
                        A + (size_t)row * NN + j0, ROWB, mb);
            }
        }
        if (++s == NS) s = 0;
    }

    // ---- epilogue: skip columns duplicated by the shifted last j-slice ----
    const bool dup = (jb == NBLK_J - 1) && (col0 < (NBLK_J - 1) * COLS);
    float part = 0.f;
    if (!dup && col0 < NN) {
        const float4* wy = (const float4*)(Y + (size_t)col0 * KK);
#pragma unroll
        for (int q = 0; q < 4; q++) {
            float4 y = wy[q];
            float2 u0 = unpack2(acc0[q * 2]);
            float2 u1 = unpack2(acc0[q * 2 + 1]);
            part += u0.x * (1.f - y.x) + u0.y * (1.f - y.y)
                  + u1.x * (1.f - y.z) + u1.y * (1.f - y.w);
        }
    }
    if (!dup && col0 + 1 < NN) {
        const float4* wy = (const float4*)(Y + (size_t)(col0 + 1) * KK);
#pragma unroll
        for (int q = 0; q < 4; q++) {
            float4 y = wy[q];
            float2 u0 = unpack2(acc1[q * 2]);
            float2 u1 = unpack2(acc1[q * 2 + 1]);
            part += u0.x * (1.f - y.x) + u0.y * (1.f - y.y)
                  + u1.x * (1.f - y.z) + u1.y * (1.f - y.w);
        }
    }

#pragma unroll
    for (int o = 16; o; o >>= 1) part += __shfl_xor_sync(0xffffffffu, part, o);
    if ((tid & 31) == 0) atomicAdd(&g_cut, (double)part);

    // last block writes scalar output
    __shared__ bool is_last;
    __threadfence();
    __syncthreads();
    if (tid == 0) {
        unsigned int old = atomicAdd(&g_ctr_m, 1u);
        is_last = (old == GRID_MAIN - 1);
    }
    __syncthreads();
    if (is_last && tid == 0) {
        __threadfence();
        double cut = *((volatile double*)&g_cut);
        out[0] = (float)(cut + (double)g_ep);
        g_ctr_m = 0u;
    }
}

extern "C" void kernel_launch(void* const* d_in, const int* in_sizes, int n_in,
                              void* d_out, int out_size) {
    const float* Y   = (const float*)d_in[0];   // [N, K]
    const float* A   = (const float*)d_in[1];   // [N, N]
    const float* deg = (const float*)d_in[2];   // [N, 1]
    float* out = (float*)d_out;

    cudaFuncSetAttribute(k_main, cudaFuncAttributeMaxDynamicSharedMemorySize,
                         SMEM_TOTAL);

    k_partial<<<PBLOCKS, 256>>>(Y, deg);
    dim3 grid(NBLK_J, NBLK_I);
    k_main<<<grid, THREADS, SMEM_TOTAL>>>(A, Y, out);
}

// round 10
// speedup vs baseline: 1.1730x; 1.1730x over previous
#include <cuda_runtime.h>
#include <cstdint>
#include <cstddef>

// Problem constants
#define NN 10000
#define KK 16
#define MEAN_NODES 625.0f

// Main kernel geometry: 24 consumer warps + 1 producer warp
#define THREADS 800
#define NWC 24                        // consumer warps
#define COLS 1536                     // cols per j-slice (24 warps x 64)
#define NBLK_J 7                      // slices; last shifted to end at 10000
#define NBLK_I 21
#define IT 480                        // rows per i-tile (21*480 = 10080)
#define RPS 4                         // rows per stage
#define NCH (IT / RPS)                // 120 chunks
#define NS 6                          // pipeline stages
#define ROWB (COLS * 4)               // 6144 B per row slice
#define STAGEB (RPS * ROWB)           // 24576 B per stage
#define PBLOCKS 40
#define GRID_MAIN (NBLK_J * NBLK_I)   // 147

// dynamic smem layout
#define SM_FULL  0                    // 6 full mbarriers
#define SM_EMPTY 48                   // 6 empty mbarriers
#define SM_STG   1024
#define SM_YN    (SM_STG + NS * STAGEB)           // 148480
#define SMEM_TOTAL (SM_YN + IT * KK * 4)          // 179200 B

// Device-global scratch
__device__ double g_cut;
__device__ float  g_invg[KK];
__device__ float  g_ep;
__device__ float  g_part[PBLOCKS * 32];
__device__ unsigned int g_ctr_p;
__device__ unsigned int g_ctr_m;

// ---- packed f32x2 helpers (Blackwell FFMA2) ----
__device__ __forceinline__ unsigned long long ffma2(unsigned long long a,
                                                    unsigned long long b,
                                                    unsigned long long c) {
    unsigned long long d;
    asm("fma.rn.f32x2 %0, %1, %2, %3;" : "=l"(d) : "l"(a), "l"(b), "l"(c));
    return d;
}
__device__ __forceinline__ unsigned long long pack2(float x, float y) {
    unsigned long long d;
    asm("mov.b64 %0, {%1, %2};" : "=l"(d) : "f"(x), "f"(y));
    return d;
}
__device__ __forceinline__ float2 unpack2(unsigned long long v) {
    float2 r;
    asm("mov.b64 {%0, %1}, %2;" : "=f"(r.x), "=f"(r.y) : "l"(v));
    return r;
}

// ---- smem / mbarrier / bulk-copy helpers ----
__device__ __forceinline__ uint32_t smem_u32(const void* p) {
    uint32_t a;
    asm("{ .reg .u64 t; cvta.to.shared.u64 t, %1; cvt.u32.u64 %0, t; }"
        : "=r"(a) : "l"(p));
    return a;
}
__device__ __forceinline__ void mbar_init(uint32_t a, uint32_t cnt) {
    asm volatile("mbarrier.init.shared.b64 [%0], %1;" :: "r"(a), "r"(cnt) : "memory");
}
__device__ __forceinline__ void mbar_expect_tx(uint32_t a, uint32_t bytes) {
    asm volatile("mbarrier.arrive.expect_tx.shared.b64 _, [%0], %1;"
                 :: "r"(a), "r"(bytes) : "memory");
}
__device__ __forceinline__ void mbar_arrive(uint32_t a) {
    asm volatile("mbarrier.arrive.shared.b64 _, [%0];" :: "r"(a) : "memory");
}
__device__ __forceinline__ void mbar_wait(uint32_t a, uint32_t parity) {
    asm volatile(
        "{\n\t.reg .pred P;\n\tLW_%=:\n\t"
        "mbarrier.try_wait.parity.acquire.cta.shared::cta.b64 P, [%0], %1, 0x989680;\n\t"
        "@!P bra LW_%=;\n\t}"
        :: "r"(a), "r"(parity) : "memory");
}
__device__ __forceinline__ void bulk_cp(uint32_t dst, const void* src,
                                        uint32_t bytes, uint32_t mbar) {
    asm volatile(
        "cp.async.bulk.shared::cluster.global.mbarrier::complete_tx::bytes "
        "[%0], [%1], %2, [%3];"
        :: "r"(dst), "l"(src), "r"(bytes), "r"(mbar) : "memory");
}

// ============================================================
// Kernel 1: partials of gamma[k] and colsum[k]; last block finalizes.
// ============================================================
__global__ void k_partial(const float* __restrict__ Y,
                          const float* __restrict__ deg) {
    int i = blockIdx.x * 256 + threadIdx.x;
    float g[KK], c[KK];
#pragma unroll
    for (int k = 0; k < KK; k++) { g[k] = 0.f; c[k] = 0.f; }

    if (i < NN) {
        float d = deg[i];
        const float4* yr = (const float4*)(Y + (size_t)i * KK);
#pragma unroll
        for (int q = 0; q < 4; q++) {
            float4 v = yr[q];
            c[q * 4 + 0] = v.x; c[q * 4 + 1] = v.y;
            c[q * 4 + 2] = v.z; c[q * 4 + 3] = v.w;
            g[q * 4 + 0] = v.x * d; g[q * 4 + 1] = v.y * d;
            g[q * 4 + 2] = v.z * d; g[q * 4 + 3] = v.w * d;
        }
    }
#pragma unroll
    for (int k = 0; k < KK; k++) {
#pragma unroll
        for (int o = 16; o; o >>= 1) {
            g[k] += __shfl_xor_sync(0xffffffffu, g[k], o);
            c[k] += __shfl_xor_sync(0xffffffffu, c[k], o);
        }
    }
    __shared__ float red[8][32];
    __shared__ bool  is_last;
    int warp = threadIdx.x >> 5, lane = threadIdx.x & 31;
    if (lane == 0) {
#pragma unroll
        for (int k = 0; k < KK; k++) {
            red[warp][k]      = g[k];
            red[warp][16 + k] = c[k];
        }
    }
    __syncthreads();
    if (threadIdx.x < 32) {
        float s = 0.f;
#pragma unroll
        for (int w = 0; w < 8; w++) s += red[w][threadIdx.x];
        g_part[blockIdx.x * 32 + threadIdx.x] = s;
    }
    __threadfence();
    if (threadIdx.x == 0) {
        unsigned int old = atomicAdd(&g_ctr_p, 1u);
        is_last = (old == PBLOCKS - 1);
    }
    __syncthreads();
    if (is_last && threadIdx.x < 32) {
        __threadfence();
        int t = threadIdx.x;
        const volatile float* gp = g_part;
        float s = 0.f;
        for (int b = 0; b < PBLOCKS; b++) s += gp[b * 32 + t];
        red[0][t] = s;
        __syncwarp();
        if (t < KK) g_invg[t] = 1.0f / s;
        if (t == 0) {
            float e = 0.f;
#pragma unroll
            for (int k = 0; k < KK; k++) {
                float d2 = red[0][16 + k] - MEAN_NODES;
                e += d2 * d2;
            }
            g_ep   = e;
            g_cut  = 0.0;
            g_ctr_p = 0u;
        }
    }
}

// ============================================================
// Kernel 2: warp-specialized pipeline. Producer warp 24 bulk-copies
// A row-slices into 6 stages; 24 consumer warps (64 cols each, CPT=2)
// compute acc[k] += A_ij * yn_jk with yn broadcast from smem.
// ============================================================
__global__ void __launch_bounds__(THREADS, 1)
k_main(const float* __restrict__ A, const float* __restrict__ Y,
       float* __restrict__ out) {
    extern __shared__ char smem[];
    const uint32_t sb  = smem_u32(smem);
    const int tid  = threadIdx.x;
    const int warp = tid >> 5;
    const int lane = tid & 31;
    const int jb   = blockIdx.x;
    const int j0   = (jb < NBLK_J - 1) ? jb * COLS : (NN - COLS);
    const int i0   = blockIdx.y * IT;

    // ---- mbarrier init: full count=1 (expect_tx arrive), empty count=24 ----
    if (tid == 0) {
#pragma unroll
        for (int s = 0; s < NS; s++) {
            mbar_init(sb + SM_FULL  + 8 * s, 1);
            mbar_init(sb + SM_EMPTY + 8 * s, NWC);
        }
    }

    // ---- cooperative yn tile: yn[i,k] = Y[i,k]*invg[k]; zero beyond NN ----
    float* sYn = (float*)(smem + SM_YN);
    {
        float4 iv[4];
#pragma unroll
        for (int q = 0; q < 4; q++) iv[q] = *(const float4*)(g_invg + q * 4);
        for (int idx = tid; idx < IT * 4; idx += THREADS) {
            int r = idx >> 2, c = idx & 3;
            int i = i0 + r;
            float4 v = make_float4(0.f, 0.f, 0.f, 0.f);
            if (i < NN) {
                float4 y = *(const float4*)(Y + (size_t)i * KK + c * 4);
                v = make_float4(y.x * iv[c].x, y.y * iv[c].y,
                                y.z * iv[c].z, y.w * iv[c].w);
            }
            *(float4*)(sYn + r * KK + c * 4) = v;
        }
    }
    __syncthreads();   // mbars + yn visible to all warps

    unsigned long long acc0[8], acc1[8];
#pragma unroll
    for (int p = 0; p < 8; p++) { acc0[p] = 0ULL; acc1[p] = 0ULL; }

    if (warp == NWC) {
        // ================= producer warp =================
        if (lane == 0) {
            // prologue: fill all NS stages
#pragma unroll
            for (int c = 0; c < NS; c++) {
                uint32_t mb = sb + SM_FULL + 8 * c;
                mbar_expect_tx(mb, STAGEB);
#pragma unroll
                for (int r = 0; r < RPS; r++) {
                    int row = i0 + c * RPS + r;
                    if (row > NN - 1) row = NN - 1;
                    bulk_cp(sb + SM_STG + c * STAGEB + r * ROWB,
                            A + (size_t)row * NN + j0, ROWB, mb);
                }
            }
            // steady state
            uint32_t eph = 0;
            int s = 0;
#pragma unroll 1
            for (int c = NS; c < NCH; c++) {
                mbar_wait(sb + SM_EMPTY + 8 * s, (eph >> s) & 1u);
                eph ^= (1u << s);
                uint32_t mb = sb + SM_FULL + 8 * s;
                mbar_expect_tx(mb, STAGEB);
#pragma unroll
                for (int r = 0; r < RPS; r++) {
                    int row = i0 + c * RPS + r;
                    if (row > NN - 1) row = NN - 1;
                    bulk_cp(sb + SM_STG + s * STAGEB + r * ROWB,
                            A + (size_t)row * NN + j0, ROWB, mb);
                }
                if (++s == NS) s = 0;
            }
        }
    } else {
        // ================= consumer warps =================
        const uint32_t abase = (uint32_t)(warp * 256 + lane * 8);
        uint32_t fph = 0;
        int s = 0;
#pragma unroll 1
        for (int c = 0; c < NCH; c++) {
            mbar_wait(sb + SM_FULL + 8 * s, (fph >> s) & 1u);
            fph ^= (1u << s);

            const char*  stg = smem + SM_STG + s * STAGEB;
            const float* syn = sYn + c * RPS * KK;
#pragma unroll
            for (int r = 0; r < RPS; r++) {
                float2 a = *(const float2*)(stg + r * ROWB + abase);
                const ulonglong2* yp = (const ulonglong2*)(syn + r * KK);
                ulonglong2 y0 = yp[0], y1 = yp[1], y2 = yp[2], y3 = yp[3];
                unsigned long long a0 = pack2(a.x, a.x);
                unsigned long long a1 = pack2(a.y, a.y);
                acc0[0] = ffma2(a0, y0.x, acc0[0]);
                acc0[1] = ffma2(a0, y0.y, acc0[1]);
                acc0[2] = ffma2(a0, y1.x, acc0[2]);
                acc0[3] = ffma2(a0, y1.y, acc0[3]);
                acc0[4] = ffma2(a0, y2.x, acc0[4]);
                acc0[5] = ffma2(a0, y2.y, acc0[5]);
                acc0[6] = ffma2(a0, y3.x, acc0[6]);
                acc0[7] = ffma2(a0, y3.y, acc0[7]);
                acc1[0] = ffma2(a1, y0.x, acc1[0]);
                acc1[1] = ffma2(a1, y0.y, acc1[1]);
                acc1[2] = ffma2(a1, y1.x, acc1[2]);
                acc1[3] = ffma2(a1, y1.y, acc1[3]);
                acc1[4] = ffma2(a1, y2.x, acc1[4]);
                acc1[5] = ffma2(a1, y2.y, acc1[5]);
                acc1[6] = ffma2(a1, y3.x, acc1[6]);
                acc1[7] = ffma2(a1, y3.y, acc1[7]);
            }
            __syncwarp();
            if (lane == 0) mbar_arrive(sb + SM_EMPTY + 8 * s);
            if (++s == NS) s = 0;
        }
    }

    // ---- epilogue ----
    const int  col0 = j0 + warp * 64 + lane * 2;   // consumer warps only
    const bool dup  = (jb == NBLK_J - 1) && (col0 < (NBLK_J - 1) * COLS);
    float part = 0.f;
    if (warp < NWC && !dup && col0 < NN) {
        const float4* wy = (const float4*)(Y + (size_t)col0 * KK);
#pragma unroll
        for (int q = 0; q < 4; q++) {
            float4 y = wy[q];
            float2 u0 = unpack2(acc0[q * 2]);
            float2 u1 = unpack2(acc0[q * 2 + 1]);
            part += u0.x * (1.f - y.x) + u0.y * (1.f - y.y)
                  + u1.x * (1.f - y.z) + u1.y * (1.f - y.w);
        }
    }
    if (warp < NWC && !dup && col0 + 1 < NN) {
        const float4* wy = (const float4*)(Y + (size_t)(col0 + 1) * KK);
#pragma unroll
        for (int q = 0; q < 4; q++) {
            float4 y = wy[q];
            float2 u0 = unpack2(acc1[q * 2]);
            float2 u1 = unpack2(acc1[q * 2 + 1]);
            part += u0.x * (1.f - y.x) + u0.y * (1.f - y.y)
                  + u1.x * (1.f - y.z) + u1.y * (1.f - y.w);
        }
    }

#pragma unroll
    for (int o = 16; o; o >>= 1) part += __shfl_xor_sync(0xffffffffu, part, o);
    if (warp < NWC && lane == 0) atomicAdd(&g_cut, (double)part);

    // last block writes scalar output
    __shared__ bool is_last;
    __threadfence();
    __syncthreads();
    if (tid == 0) {
        unsigned int old = atomicAdd(&g_ctr_m, 1u);
        is_last = (old == GRID_MAIN - 1);
    }
    __syncthreads();
    if (is_last && tid == 0) {
        __threadfence();
        double cut = *((volatile double*)&g_cut);
        out[0] = (float)(cut + (double)g_ep);
        g_ctr_m = 0u;
    }
}

extern "C" void kernel_launch(void* const* d_in, const int* in_sizes, int n_in,
                              void* d_out, int out_size) {
    const float* Y   = (const float*)d_in[0];   // [N, K]
    const float* A   = (const float*)d_in[1];   // [N, N]
    const float* deg = (const float*)d_in[2];   // [N, 1]
    float* out = (float*)d_out;

    cudaFuncSetAttribute(k_main, cudaFuncAttributeMaxDynamicSharedMemorySize,
                         SMEM_TOTAL);

    k_partial<<<PBLOCKS, 256>>>(Y, deg);
    dim3 grid(NBLK_J, NBLK_I);
    k_main<<<grid, THREADS, SMEM_TOTAL>>>(A, Y, out);
}

// round 11
// speedup vs baseline: 1.2504x; 1.0659x over previous
#include <cuda_runtime.h>
#include <cstdint>
#include <cstddef>

// Problem constants
#define NN 10000
#define KK 16
#define MEAN_NODES 625.0f

// Main kernel geometry: 24 consumer warps + 1 producer warp
#define THREADS 800
#define NWC 24                        // consumer warps
#define COLS 1536                     // cols per j-slice (24 warps x 64)
#define NBLK_J 7                      // slices; last shifted to end at 10000
#define NBLK_I 21
#define IT 480                        // rows per i-tile (21*480 = 10080)
#define RPS 8                         // rows per stage
#define NCH (IT / RPS)                // 60 chunks
#define NS 3                          // pipeline stages
#define ROWB (COLS * 4)               // 6144 B per row slice
#define STAGEB (RPS * ROWB)           // 49152 B per stage
#define PBLOCKS 40
#define GRID_MAIN (NBLK_J * NBLK_I)   // 147

// dynamic smem layout
#define SM_FULL  0                    // 3 full mbarriers
#define SM_EMPTY 48                   // 3 empty mbarriers
#define SM_STG   1024
#define SM_YN    (SM_STG + NS * STAGEB)           // 148480
#define SMEM_TOTAL (SM_YN + IT * KK * 4)          // 179200 B

// Device-global scratch
__device__ double g_cut;
__device__ float  g_invg[KK];
__device__ float  g_ep;
__device__ float  g_part[PBLOCKS * 32];
__device__ unsigned int g_ctr_p;
__device__ unsigned int g_ctr_m;

// ---- packed f32x2 helpers (Blackwell FFMA2) ----
__device__ __forceinline__ unsigned long long ffma2(unsigned long long a,
                                                    unsigned long long b,
                                                    unsigned long long c) {
    unsigned long long d;
    asm("fma.rn.f32x2 %0, %1, %2, %3;" : "=l"(d) : "l"(a), "l"(b), "l"(c));
    return d;
}
__device__ __forceinline__ unsigned long long pack2(float x, float y) {
    unsigned long long d;
    asm("mov.b64 %0, {%1, %2};" : "=l"(d) : "f"(x), "f"(y));
    return d;
}
__device__ __forceinline__ float2 unpack2(unsigned long long v) {
    float2 r;
    asm("mov.b64 {%0, %1}, %2;" : "=f"(r.x), "=f"(r.y) : "l"(v));
    return r;
}

// ---- smem / mbarrier / bulk-copy helpers ----
__device__ __forceinline__ uint32_t smem_u32(const void* p) {
    uint32_t a;
    asm("{ .reg .u64 t; cvta.to.shared.u64 t, %1; cvt.u32.u64 %0, t; }"
        : "=r"(a) : "l"(p));
    return a;
}
__device__ __forceinline__ void mbar_init(uint32_t a, uint32_t cnt) {
    asm volatile("mbarrier.init.shared.b64 [%0], %1;" :: "r"(a), "r"(cnt) : "memory");
}
__device__ __forceinline__ void mbar_expect_tx(uint32_t a, uint32_t bytes) {
    asm volatile("mbarrier.arrive.expect_tx.shared.b64 _, [%0], %1;"
                 :: "r"(a), "r"(bytes) : "memory");
}
__device__ __forceinline__ void mbar_arrive(uint32_t a) {
    asm volatile("mbarrier.arrive.shared.b64 _, [%0];" :: "r"(a) : "memory");
}
__device__ __forceinline__ void mbar_wait(uint32_t a, uint32_t parity) {
    asm volatile(
        "{\n\t.reg .pred P;\n\tLW_%=:\n\t"
        "mbarrier.try_wait.parity.acquire.cta.shared::cta.b64 P, [%0], %1, 0x989680;\n\t"
        "@!P bra LW_%=;\n\t}"
        :: "r"(a), "r"(parity) : "memory");
}
__device__ __forceinline__ void bulk_cp(uint32_t dst, const void* src,
                                        uint32_t bytes, uint32_t mbar) {
    asm volatile(
        "cp.async.bulk.shared::cluster.global.mbarrier::complete_tx::bytes "
        "[%0], [%1], %2, [%3];"
        :: "r"(dst), "l"(src), "r"(bytes), "r"(mbar) : "memory");
}

// ============================================================
// Kernel 1: partials of gamma[k] and colsum[k]; last block finalizes.
// ============================================================
__global__ void k_partial(const float* __restrict__ Y,
                          const float* __restrict__ deg) {
    int i = blockIdx.x * 256 + threadIdx.x;
    float g[KK], c[KK];
#pragma unroll
    for (int k = 0; k < KK; k++) { g[k] = 0.f; c[k] = 0.f; }

    if (i < NN) {
        float d = deg[i];
        const float4* yr = (const float4*)(Y + (size_t)i * KK);
#pragma unroll
        for (int q = 0; q < 4; q++) {
            float4 v = yr[q];
            c[q * 4 + 0] = v.x; c[q * 4 + 1] = v.y;
            c[q * 4 + 2] = v.z; c[q * 4 + 3] = v.w;
            g[q * 4 + 0] = v.x * d; g[q * 4 + 1] = v.y * d;
            g[q * 4 + 2] = v.z * d; g[q * 4 + 3] = v.w * d;
        }
    }
#pragma unroll
    for (int k = 0; k < KK; k++) {
#pragma unroll
        for (int o = 16; o; o >>= 1) {
            g[k] += __shfl_xor_sync(0xffffffffu, g[k], o);
            c[k] += __shfl_xor_sync(0xffffffffu, c[k], o);
        }
    }
    __shared__ float red[8][32];
    __shared__ bool  is_last;
    int warp = threadIdx.x >> 5, lane = threadIdx.x & 31;
    if (lane == 0) {
#pragma unroll
        for (int k = 0; k < KK; k++) {
            red[warp][k]      = g[k];
            red[warp][16 + k] = c[k];
        }
    }
    __syncthreads();
    if (threadIdx.x < 32) {
        float s = 0.f;
#pragma unroll
        for (int w = 0; w < 8; w++) s += red[w][threadIdx.x];
        g_part[blockIdx.x * 32 + threadIdx.x] = s;
    }
    __threadfence();
    if (threadIdx.x == 0) {
        unsigned int old = atomicAdd(&g_ctr_p, 1u);
        is_last = (old == PBLOCKS - 1);
    }
    __syncthreads();
    if (is_last && threadIdx.x < 32) {
        __threadfence();
        int t = threadIdx.x;
        const volatile float* gp = g_part;
        float s = 0.f;
        for (int b = 0; b < PBLOCKS; b++) s += gp[b * 32 + t];
        red[0][t] = s;
        __syncwarp();
        if (t < KK) g_invg[t] = 1.0f / s;
        if (t == 0) {
            float e = 0.f;
#pragma unroll
            for (int k = 0; k < KK; k++) {
                float d2 = red[0][16 + k] - MEAN_NODES;
                e += d2 * d2;
            }
            g_ep   = e;
            g_cut  = 0.0;
            g_ctr_p = 0u;
        }
    }
}

// ============================================================
// Kernel 2: warp-specialized pipeline. Producer warp bulk-copies
// 8-row A slices into 3 stages; 24 consumer warps (64 cols, CPT=2)
// compute acc[k] += A_ij * yn_jk with yn broadcast from smem.
// ============================================================
__global__ void __launch_bounds__(THREADS, 1)
k_main(const float* __restrict__ A, const float* __restrict__ Y,
       float* __restrict__ out) {
    extern __shared__ char smem[];
    const uint32_t sb  = smem_u32(smem);
    const int tid  = threadIdx.x;
    const int warp = tid >> 5;
    const int lane = tid & 31;
    const int jb   = blockIdx.x;
    const int j0   = (jb < NBLK_J - 1) ? jb * COLS : (NN - COLS);
    const int i0   = blockIdx.y * IT;

    // ---- mbarrier init: full count=1 (expect_tx arrive), empty count=24 ----
    if (tid == 0) {
#pragma unroll
        for (int s = 0; s < NS; s++) {
            mbar_init(sb + SM_FULL  + 8 * s, 1);
            mbar_init(sb + SM_EMPTY + 8 * s, NWC);
        }
    }

    // ---- cooperative yn tile: yn[i,k] = Y[i,k]*invg[k]; zero beyond NN ----
    float* sYn = (float*)(smem + SM_YN);
    {
        float4 iv[4];
#pragma unroll
        for (int q = 0; q < 4; q++) iv[q] = *(const float4*)(g_invg + q * 4);
        for (int idx = tid; idx < IT * 4; idx += THREADS) {
            int r = idx >> 2, c = idx & 3;
            int i = i0 + r;
            float4 v = make_float4(0.f, 0.f, 0.f, 0.f);
            if (i < NN) {
                float4 y = *(const float4*)(Y + (size_t)i * KK + c * 4);
                v = make_float4(y.x * iv[c].x, y.y * iv[c].y,
                                y.z * iv[c].z, y.w * iv[c].w);
            }
            *(float4*)(sYn + r * KK + c * 4) = v;
        }
    }
    __syncthreads();   // mbars + yn visible to all warps

    unsigned long long acc0[8], acc1[8];
#pragma unroll
    for (int p = 0; p < 8; p++) { acc0[p] = 0ULL; acc1[p] = 0ULL; }

    if (warp == NWC) {
        // ================= producer warp =================
        if (lane == 0) {
            // prologue: fill all NS stages
#pragma unroll
            for (int c = 0; c < NS; c++) {
                uint32_t mb = sb + SM_FULL + 8 * c;
                mbar_expect_tx(mb, STAGEB);
#pragma unroll
                for (int r = 0; r < RPS; r++) {
                    int row = i0 + c * RPS + r;
                    if (row > NN - 1) row = NN - 1;
                    bulk_cp(sb + SM_STG + c * STAGEB + r * ROWB,
                            A + (size_t)row * NN + j0, ROWB, mb);
                }
            }
            // steady state
            uint32_t eph = 0;
            int s = 0;
#pragma unroll 1
            for (int c = NS; c < NCH; c++) {
                mbar_wait(sb + SM_EMPTY + 8 * s, (eph >> s) & 1u);
                eph ^= (1u << s);
                uint32_t mb = sb + SM_FULL + 8 * s;
                mbar_expect_tx(mb, STAGEB);
#pragma unroll
                for (int r = 0; r < RPS; r++) {
                    int row = i0 + c * RPS + r;
                    if (row > NN - 1) row = NN - 1;
                    bulk_cp(sb + SM_STG + s * STAGEB + r * ROWB,
                            A + (size_t)row * NN + j0, ROWB, mb);
                }
                if (++s == NS) s = 0;
            }
        }
    } else {
        // ================= consumer warps =================
        const uint32_t abase = (uint32_t)(warp * 256 + lane * 8);
        uint32_t fph = 0;
        int s = 0;
#pragma unroll 1
        for (int c = 0; c < NCH; c++) {
            mbar_wait(sb + SM_FULL + 8 * s, (fph >> s) & 1u);
            fph ^= (1u << s);

            const char*  stg = smem + SM_STG + s * STAGEB;
            const float* syn = sYn + c * RPS * KK;
#pragma unroll
            for (int r = 0; r < RPS; r++) {
                float2 a = *(const float2*)(stg + r * ROWB + abase);
                const ulonglong2* yp = (const ulonglong2*)(syn + r * KK);
                ulonglong2 y0 = yp[0], y1 = yp[1], y2 = yp[2], y3 = yp[3];
                unsigned long long a0 = pack2(a.x, a.x);
                unsigned long long a1 = pack2(a.y, a.y);
                acc0[0] = ffma2(a0, y0.x, acc0[0]);
                acc0[1] = ffma2(a0, y0.y, acc0[1]);
                acc0[2] = ffma2(a0, y1.x, acc0[2]);
                acc0[3] = ffma2(a0, y1.y, acc0[3]);
                acc0[4] = ffma2(a0, y2.x, acc0[4]);
                acc0[5] = ffma2(a0, y2.y, acc0[5]);
                acc0[6] = ffma2(a0, y3.x, acc0[6]);
                acc0[7] = ffma2(a0, y3.y, acc0[7]);
                acc1[0] = ffma2(a1, y0.x, acc1[0]);
                acc1[1] = ffma2(a1, y0.y, acc1[1]);
                acc1[2] = ffma2(a1, y1.x, acc1[2]);
                acc1[3] = ffma2(a1, y1.y, acc1[3]);
                acc1[4] = ffma2(a1, y2.x, acc1[4]);
                acc1[5] = ffma2(a1, y2.y, acc1[5]);
                acc1[6] = ffma2(a1, y3.x, acc1[6]);
                acc1[7] = ffma2(a1, y3.y, acc1[7]);
            }
            __syncwarp();
            if (lane == 0) mbar_arrive(sb + SM_EMPTY + 8 * s);
            if (++s == NS) s = 0;
        }
    }

    // ---- epilogue ----
    const int  col0 = j0 + warp * 64 + lane * 2;   // consumer warps only
    const bool dup  = (jb == NBLK_J - 1) && (col0 < (NBLK_J - 1) * COLS);
    float part = 0.f;
    if (warp < NWC && !dup && col0 < NN) {
        const float4* wy = (const float4*)(Y + (size_t)col0 * KK);
#pragma unroll
        for (int q = 0; q < 4; q++) {
            float4 y = wy[q];
            float2 u0 = unpack2(acc0[q * 2]);
            float2 u1 = unpack2(acc0[q * 2 + 1]);
            part += u0.x * (1.f - y.x) + u0.y * (1.f - y.y)
                  + u1.x * (1.f - y.z) + u1.y * (1.f - y.w);
        }
    }
    if (warp < NWC && !dup && col0 + 1 < NN) {
        const float4* wy = (const float4*)(Y + (size_t)(col0 + 1) * KK);
#pragma unroll
        for (int q = 0; q < 4; q++) {
            float4 y = wy[q];
            float2 u0 = unpack2(acc1[q * 2]);
            float2 u1 = unpack2(acc1[q * 2 + 1]);
            part += u0.x * (1.f - y.x) + u0.y * (1.f - y.y)
                  + u1.x * (1.f - y.z) + u1.y * (1.f - y.w);
        }
    }

#pragma unroll
    for (int o = 16; o; o >>= 1) part += __shfl_xor_sync(0xffffffffu, part, o);
    if (warp < NWC && lane == 0) atomicAdd(&g_cut, (double)part);

    // last block writes scalar output
    __shared__ bool is_last;
    __threadfence();
    __syncthreads();
    if (tid == 0) {
        unsigned int old = atomicAdd(&g_ctr_m, 1u);
        is_last = (old == GRID_MAIN - 1);
    }
    __syncthreads();
    if (is_last && tid == 0) {
        __threadfence();
        double cut = *((volatile double*)&g_cut);
        out[0] = (float)(cut + (double)g_ep);
        g_ctr_m = 0u;
    }
}

extern "C" void kernel_launch(void* const* d_in, const int* in_sizes, int n_in,
                              void* d_out, int out_size) {
    const float* Y   = (const float*)d_in[0];   // [N, K]
    const float* A   = (const float*)d_in[1];   // [N, N]
    const float* deg = (const float*)d_in[2];   // [N, 1]
    float* out = (float*)d_out;

    cudaFuncSetAttribute(k_main, cudaFuncAttributeMaxDynamicSharedMemorySize,
                         SMEM_TOTAL);

    k_partial<<<PBLOCKS, 256>>>(Y, deg);
    dim3 grid(NBLK_J, NBLK_I);
    k_main<<<grid, THREADS, SMEM_TOTAL>>>(A, Y, out);
}